// round 2
// baseline (speedup 1.0000x reference)
#include <cuda_runtime.h>
#include <cstdint>

// Problem constants (fixed by the reference)
#define N_NODES 100000
#define IN_F    256
#define OUT_F   128
#define N_EDGES 3200000

// Scratch for h = x @ W + b  (51.2 MB) — __device__ global per allocation rules.
__device__ float g_h[(size_t)N_NODES * OUT_F];

// ---------------------------------------------------------------------------
// Kernel 1: zero the output (harness poisons d_out with 0xAA)
// ---------------------------------------------------------------------------
__global__ void zero_out_kernel(float4* __restrict__ out, int n4) {
    int i = blockIdx.x * blockDim.x + threadIdx.x;
    int stride = gridDim.x * blockDim.x;
    float4 z = make_float4(0.f, 0.f, 0.f, 0.f);
    for (; i < n4; i += stride) out[i] = z;
}

// ---------------------------------------------------------------------------
// Kernel 2: h = x @ W + bias
//   x: [M, 256] row-major, W: [256, 128] row-major, h: [M, 128]
//   Block tile: 64 (M) x 128 (N), BK = 32. 256 threads, each 8x4 outputs.
// ---------------------------------------------------------------------------
#define BM 64
#define BN 128
#define BK 32

__global__ __launch_bounds__(256)
void gemm_bias_kernel(const float* __restrict__ X,
                      const float* __restrict__ W,
                      const float* __restrict__ B,
                      int M) {
    __shared__ float As[BM][BK + 4];   // pad=4 keeps float4 16B alignment, kills bank conflicts
    __shared__ float Bs[BK][BN];

    const int t = threadIdx.x;            // 0..255
    const int blockRow = blockIdx.x * BM;
    const int colGroup = t & 31;          // 0..31 -> columns colGroup*4 .. +3
    const int rowGroup = t >> 5;          // 0..7  -> rows rowGroup*8 .. +7

    float acc[8][4];
#pragma unroll
    for (int r = 0; r < 8; r++)
#pragma unroll
        for (int c = 0; c < 4; c++) acc[r][c] = 0.f;

    for (int k0 = 0; k0 < IN_F; k0 += BK) {
        // --- load A tile: 64x32 floats = 512 float4, 2 per thread ---
#pragma unroll
        for (int i = 0; i < 2; i++) {
            int idx = t + i * 256;            // 0..511
            int arow = idx >> 3;              // 0..63
            int acol4 = idx & 7;              // 0..7 (float4 slots)
            int grow = blockRow + arow;
            float4 v = make_float4(0.f, 0.f, 0.f, 0.f);
            if (grow < M)
                v = *reinterpret_cast<const float4*>(X + (size_t)grow * IN_F + k0 + acol4 * 4);
            *reinterpret_cast<float4*>(&As[arow][acol4 * 4]) = v;
        }
        // --- load B tile: 32x128 floats = 1024 float4, 4 per thread ---
#pragma unroll
        for (int i = 0; i < 4; i++) {
            int idx = t + i * 256;            // 0..1023
            int brow = idx >> 5;              // 0..31
            int bcol4 = idx & 31;             // 0..31
            float4 v = *reinterpret_cast<const float4*>(W + (size_t)(k0 + brow) * OUT_F + bcol4 * 4);
            *reinterpret_cast<float4*>(&Bs[brow][bcol4 * 4]) = v;
        }
        __syncthreads();

#pragma unroll
        for (int kk = 0; kk < BK; kk++) {
            float a[8];
#pragma unroll
            for (int r = 0; r < 8; r++) a[r] = As[rowGroup * 8 + r][kk];
            float4 b = *reinterpret_cast<const float4*>(&Bs[kk][colGroup * 4]);
#pragma unroll
            for (int r = 0; r < 8; r++) {
                acc[r][0] = fmaf(a[r], b.x, acc[r][0]);
                acc[r][1] = fmaf(a[r], b.y, acc[r][1]);
                acc[r][2] = fmaf(a[r], b.z, acc[r][2]);
                acc[r][3] = fmaf(a[r], b.w, acc[r][3]);
            }
        }
        __syncthreads();
    }

    // epilogue: add bias, store to g_h
    float4 bb = *reinterpret_cast<const float4*>(B + colGroup * 4);
#pragma unroll
    for (int r = 0; r < 8; r++) {
        int grow = blockRow + rowGroup * 8 + r;
        if (grow < M) {
            float4 v;
            v.x = acc[r][0] + bb.x;
            v.y = acc[r][1] + bb.y;
            v.z = acc[r][2] + bb.z;
            v.w = acc[r][3] + bb.w;
            *reinterpret_cast<float4*>(&g_h[(size_t)grow * OUT_F + colGroup * 4]) = v;
        }
    }
}

// ---------------------------------------------------------------------------
// Kernel 3: SpMM scatter — one warp per edge, one float4 (4 cols) per lane.
//   out[dst[e]] += vals[e] * h[src[e]]   (128 floats per edge)
// ---------------------------------------------------------------------------
__global__ __launch_bounds__(256)
void spmm_kernel(const int* __restrict__ src,
                 const int* __restrict__ dst,
                 const float* __restrict__ vals,
                 float* __restrict__ out,
                 int nEdges) {
    int warpId = (blockIdx.x * blockDim.x + threadIdx.x) >> 5;
    int lane = threadIdx.x & 31;
    if (warpId >= nEdges) return;

    int s = src[warpId];      // warp-broadcast loads (all lanes same address)
    int d = dst[warpId];
    float v = vals[warpId];

    float4 m = *reinterpret_cast<const float4*>(g_h + (size_t)s * OUT_F + lane * 4);
    m.x *= v; m.y *= v; m.z *= v; m.w *= v;

    float* o = out + (size_t)d * OUT_F + lane * 4;
    // vector reduction, no return value (sm_90+)
    asm volatile("red.global.add.v4.f32 [%0], {%1, %2, %3, %4};"
                 :: "l"(o), "f"(m.x), "f"(m.y), "f"(m.z), "f"(m.w)
                 : "memory");
}

// ---------------------------------------------------------------------------
// Launch
//   inputs (metadata order): x, edge_src, edge_dst, edge_vals, weight, bias
// ---------------------------------------------------------------------------
extern "C" void kernel_launch(void* const* d_in, const int* in_sizes, int n_in,
                              void* d_out, int out_size) {
    const float* x        = (const float*)d_in[0];
    const int*   edge_src = (const int*)d_in[1];
    const int*   edge_dst = (const int*)d_in[2];
    const float* edge_val = (const float*)d_in[3];
    const float* weight   = (const float*)d_in[4];
    const float* bias     = (const float*)d_in[5];
    float*       out      = (float*)d_out;

    const int M = in_sizes[0] / IN_F;          // 100000
    const int E = in_sizes[1];                 // 3200000

    // 1) zero output
    {
        int n4 = out_size / 4;
        int threads = 256;
        int blocks = 2048;
        zero_out_kernel<<<blocks, threads>>>((float4*)out, n4);
    }

    // 2) h = x @ W + b
    {
        int blocks = (M + BM - 1) / BM;        // 1563
        gemm_bias_kernel<<<blocks, 256>>>(x, weight, bias, M);
    }

    // 3) scatter-add over edges
    {
        long long totalThreads = (long long)E * 32;
        int threads = 256;
        int blocks = (int)((totalThreads + threads - 1) / threads);  // 400000
        spmm_kernel<<<blocks, threads>>>(edge_src, edge_dst, edge_val, out, E);
    }
}

// round 3
// speedup vs baseline: 1.2670x; 1.2670x over previous
#include <cuda_runtime.h>
#include <cuda_bf16.h>
#include <mma.h>
#include <cstdint>

using namespace nvcuda;

// Problem constants (fixed by the reference)
#define N_NODES 100000
#define IN_F    256
#define OUT_F   128
#define N_EDGES 3200000

// Scratch for h = x @ W + b  (51.2 MB) — __device__ global per allocation rules.
__device__ float g_h[(size_t)N_NODES * OUT_F];

// ---------------------------------------------------------------------------
// Kernel 1: zero the output (harness poisons d_out with 0xAA)
// ---------------------------------------------------------------------------
__global__ void zero_out_kernel(float4* __restrict__ out, int n4) {
    int i = blockIdx.x * blockDim.x + threadIdx.x;
    int stride = gridDim.x * blockDim.x;
    float4 z = make_float4(0.f, 0.f, 0.f, 0.f);
    for (; i < n4; i += stride) out[i] = z;
}

// ---------------------------------------------------------------------------
// Kernel 2: h = x @ W + bias  via bf16 split-precision tensor-core MMA.
//   Each fp32 a = a_hi + a_lo (two bf16). Compute:
//     a*b ~= a_hi*b_hi + a_hi*b_lo + a_lo*b_hi   (fp32 accumulate)
//   Block tile: 64(M) x 128(N), BK=32. 8 warps: 4 along M x 2 along N.
//   Each warp: 16x64 output = 4 wmma 16x16 accumulators.
// ---------------------------------------------------------------------------
#define BM 64
#define BN 128
#define BK 32

__global__ __launch_bounds__(256)
void gemm_bias_tc_kernel(const float* __restrict__ X,
                         const float* __restrict__ W,
                         const float* __restrict__ B,
                         int M) {
    // Pads chosen for conflict-free ldmatrix phases:
    //  A stride 40 bf16 = 80B  -> i*80 mod 128 distinct over 8 rows
    //  B stride 136 bf16 = 272B -> i*272 mod 128 = i*16, distinct over 8 rows
    __shared__ __nv_bfloat16 AsHi[BM][40];
    __shared__ __nv_bfloat16 AsLo[BM][40];
    __shared__ __nv_bfloat16 BsHi[BK][136];
    __shared__ __nv_bfloat16 BsLo[BK][136];
    __shared__ float patch[8][16][20];   // per-warp 16x16 staging (pad 20)

    const int t = threadIdx.x;            // 0..255
    const int blockRow = blockIdx.x * BM;
    const int w = t >> 5;                 // warp 0..7
    const int warpM = w >> 1;             // 0..3  (rows warpM*16)
    const int warpN = w & 1;              // 0..1  (cols warpN*64)

    wmma::fragment<wmma::accumulator, 16, 16, 16, float> acc[4];
#pragma unroll
    for (int n = 0; n < 4; n++) wmma::fill_fragment(acc[n], 0.0f);

    for (int k0 = 0; k0 < IN_F; k0 += BK) {
        // --- A tile: 64x32 fp32 -> hi/lo bf16. 512 float4, 2 per thread ---
#pragma unroll
        for (int i = 0; i < 2; i++) {
            int idx = t + i * 256;             // 0..511
            int arow = idx >> 3;               // 0..63
            int acol = (idx & 7) * 4;          // 0,4,..28
            int grow = blockRow + arow;
            float4 v = make_float4(0.f, 0.f, 0.f, 0.f);
            if (grow < M)
                v = *reinterpret_cast<const float4*>(X + (size_t)grow * IN_F + k0 + acol);
            float vv[4] = {v.x, v.y, v.z, v.w};
#pragma unroll
            for (int j = 0; j < 4; j++) {
                __nv_bfloat16 hi = __float2bfloat16(vv[j]);
                __nv_bfloat16 lo = __float2bfloat16(vv[j] - __bfloat162float(hi));
                AsHi[arow][acol + j] = hi;
                AsLo[arow][acol + j] = lo;
            }
        }
        // --- B tile: 32x128 fp32 -> hi/lo bf16. 1024 float4, 4 per thread ---
#pragma unroll
        for (int i = 0; i < 4; i++) {
            int idx = t + i * 256;             // 0..1023
            int brow = idx >> 5;               // 0..31
            int bcol = (idx & 31) * 4;         // 0..124
            float4 v = *reinterpret_cast<const float4*>(W + (size_t)(k0 + brow) * OUT_F + bcol);
            float vv[4] = {v.x, v.y, v.z, v.w};
#pragma unroll
            for (int j = 0; j < 4; j++) {
                __nv_bfloat16 hi = __float2bfloat16(vv[j]);
                __nv_bfloat16 lo = __float2bfloat16(vv[j] - __bfloat162float(hi));
                BsHi[brow][bcol + j] = hi;
                BsLo[brow][bcol + j] = lo;
            }
        }
        __syncthreads();

#pragma unroll
        for (int kk = 0; kk < BK; kk += 16) {
            wmma::fragment<wmma::matrix_a, 16, 16, 16, __nv_bfloat16, wmma::row_major> aHi, aLo;
            wmma::load_matrix_sync(aHi, &AsHi[warpM * 16][kk], 40);
            wmma::load_matrix_sync(aLo, &AsLo[warpM * 16][kk], 40);
#pragma unroll
            for (int n = 0; n < 4; n++) {
                wmma::fragment<wmma::matrix_b, 16, 16, 16, __nv_bfloat16, wmma::row_major> bHi, bLo;
                int col = warpN * 64 + n * 16;
                wmma::load_matrix_sync(bHi, &BsHi[kk][col], 136);
                wmma::load_matrix_sync(bLo, &BsLo[kk][col], 136);
                wmma::mma_sync(acc[n], aHi, bHi, acc[n]);
                wmma::mma_sync(acc[n], aHi, bLo, acc[n]);
                wmma::mma_sync(acc[n], aLo, bHi, acc[n]);
            }
        }
        __syncthreads();
    }

    // Epilogue: stage each 16x16 acc via smem, add bias, store float4.
    const int lane = t & 31;
#pragma unroll
    for (int n = 0; n < 4; n++) {
        wmma::store_matrix_sync(&patch[w][0][0], acc[n], 20, wmma::mem_row_major);
        __syncwarp();
        int r = lane >> 1;                    // 0..15
        int cbase = (lane & 1) * 8;           // 0 or 8
        int grow = blockRow + warpM * 16 + r;
        int gcolBase = warpN * 64 + n * 16 + cbase;
        if (grow < M) {
#pragma unroll
            for (int j = 0; j < 2; j++) {
                float4 v;
                v.x = patch[w][r][cbase + j * 4 + 0] + __ldg(B + gcolBase + j * 4 + 0);
                v.y = patch[w][r][cbase + j * 4 + 1] + __ldg(B + gcolBase + j * 4 + 1);
                v.z = patch[w][r][cbase + j * 4 + 2] + __ldg(B + gcolBase + j * 4 + 2);
                v.w = patch[w][r][cbase + j * 4 + 3] + __ldg(B + gcolBase + j * 4 + 3);
                *reinterpret_cast<float4*>(&g_h[(size_t)grow * OUT_F + gcolBase + j * 4]) = v;
            }
        }
        __syncwarp();
    }
}

// ---------------------------------------------------------------------------
// Kernel 3: SpMM scatter. Block = 256 threads = 256 edges.
//   Each thread loads one edge's metadata coalesced; warp then iterates its
//   32 edges via shfl broadcast. One float4 (4 cols) per lane per edge.
// ---------------------------------------------------------------------------
__global__ __launch_bounds__(256)
void spmm_kernel(const int* __restrict__ src,
                 const int* __restrict__ dst,
                 const float* __restrict__ vals,
                 float* __restrict__ out,
                 int nEdges) {
    const int e = blockIdx.x * 256 + threadIdx.x;
    const int lane = threadIdx.x & 31;
    const int warpBase = (blockIdx.x * 256) + (threadIdx.x & ~31);

    int s = 0, d = 0;
    float v = 0.f;
    if (e < nEdges) { s = src[e]; d = dst[e]; v = vals[e]; }

#pragma unroll 4
    for (int i = 0; i < 32; i++) {
        int   si = __shfl_sync(0xffffffffu, s, i);
        int   di = __shfl_sync(0xffffffffu, d, i);
        float vi = __shfl_sync(0xffffffffu, v, i);
        if (warpBase + i < nEdges) {
            float4 m = *reinterpret_cast<const float4*>(g_h + (size_t)si * OUT_F + lane * 4);
            m.x *= vi; m.y *= vi; m.z *= vi; m.w *= vi;
            float* o = out + (size_t)di * OUT_F + lane * 4;
            asm volatile("red.global.add.v4.f32 [%0], {%1, %2, %3, %4};"
                         :: "l"(o), "f"(m.x), "f"(m.y), "f"(m.z), "f"(m.w)
                         : "memory");
        }
    }
}

// ---------------------------------------------------------------------------
// Launch
//   inputs (metadata order): x, edge_src, edge_dst, edge_vals, weight, bias
// ---------------------------------------------------------------------------
extern "C" void kernel_launch(void* const* d_in, const int* in_sizes, int n_in,
                              void* d_out, int out_size) {
    const float* x        = (const float*)d_in[0];
    const int*   edge_src = (const int*)d_in[1];
    const int*   edge_dst = (const int*)d_in[2];
    const float* edge_val = (const float*)d_in[3];
    const float* weight   = (const float*)d_in[4];
    const float* bias     = (const float*)d_in[5];
    float*       out      = (float*)d_out;

    const int M = in_sizes[0] / IN_F;          // 100000
    const int E = in_sizes[1];                 // 3200000

    // 1) zero output
    {
        int n4 = out_size / 4;
        zero_out_kernel<<<2048, 256>>>((float4*)out, n4);
    }

    // 2) h = x @ W + b  (tensor cores, bf16x3 split)
    {
        int blocks = (M + BM - 1) / BM;        // 1563
        gemm_bias_tc_kernel<<<blocks, 256>>>(x, weight, bias, M);
    }

    // 3) scatter-add over edges
    {
        int blocks = (E + 255) / 256;          // 12500
        spmm_kernel<<<blocks, 256>>>(edge_src, edge_dst, edge_val, out, E);
    }
}

// round 7
// speedup vs baseline: 1.9225x; 1.5173x over previous
#include <cuda_runtime.h>
#include <cuda_bf16.h>
#include <mma.h>
#include <cstdint>

using namespace nvcuda;

#define N_NODES 100000
#define IN_F    256
#define OUT_F   128
#define N_EDGES 3200000

// ---- scratch (device globals per allocation rules) ----
__device__ float        g_h[(size_t)N_NODES * OUT_F];     // xW (no bias), 51.2 MB
__device__ int2         g_edges[N_EDGES];                 // dst-sorted (src, valbits), 25.6 MB
__device__ int          g_hist[N_NODES];
__device__ int          g_locExc[N_NODES];
__device__ int          g_blockSums[512];
__device__ int          g_offsets[N_NODES];
__device__ int          g_cursor[N_NODES];
__device__ __nv_bfloat16 g_Whi[IN_F * OUT_F];
__device__ __nv_bfloat16 g_Wlo[IN_F * OUT_F];

// ---------------------------------------------------------------------------
// W -> (hi, lo) bf16 split, done once (32K elements)
// ---------------------------------------------------------------------------
__global__ void convert_w_kernel(const float* __restrict__ W) {
    int i = blockIdx.x * blockDim.x + threadIdx.x;
    if (i < IN_F * OUT_F) {
        float w = W[i];
        __nv_bfloat16 hi = __float2bfloat16(w);
        __nv_bfloat16 lo = __float2bfloat16(w - __bfloat162float(hi));
        g_Whi[i] = hi;
        g_Wlo[i] = lo;
    }
}

// ---------------------------------------------------------------------------
// Counting sort of edges by dst
// ---------------------------------------------------------------------------
__global__ void zero_hist_kernel() {
    int i = blockIdx.x * blockDim.x + threadIdx.x;
    int stride = gridDim.x * blockDim.x;
    for (; i < N_NODES; i += stride) g_hist[i] = 0;
}

__global__ void hist_kernel(const int* __restrict__ dst, int E) {
    int e = blockIdx.x * blockDim.x + threadIdx.x;
    if (e < E) atomicAdd(&g_hist[dst[e]], 1);
}

// per-block exclusive scan (256 elems), emit block totals
__global__ void scan1_kernel(int n) {
    __shared__ int sm[256];
    int i = blockIdx.x * 256 + threadIdx.x;
    int v = (i < n) ? g_hist[i] : 0;
    sm[threadIdx.x] = v;
    __syncthreads();
#pragma unroll
    for (int off = 1; off < 256; off <<= 1) {
        int add = (threadIdx.x >= off) ? sm[threadIdx.x - off] : 0;
        __syncthreads();
        sm[threadIdx.x] += add;
        __syncthreads();
    }
    if (i < n) g_locExc[i] = sm[threadIdx.x] - v;     // exclusive
    if (threadIdx.x == 255) g_blockSums[blockIdx.x] = sm[255];
}

// single-block exclusive scan of block sums (nb <= 512)
__global__ void scan2_kernel(int nb) {
    __shared__ int sm[512];
    int t = threadIdx.x;
    int v = (t < nb) ? g_blockSums[t] : 0;
    sm[t] = v;
    __syncthreads();
#pragma unroll
    for (int off = 1; off < 512; off <<= 1) {
        int add = (t >= off) ? sm[t - off] : 0;
        __syncthreads();
        sm[t] += add;
        __syncthreads();
    }
    g_blockSums[t] = sm[t] - v;                        // exclusive
}

__global__ void scan3_kernel(int n) {
    int i = blockIdx.x * blockDim.x + threadIdx.x;
    if (i < n) {
        int o = g_locExc[i] + g_blockSums[i >> 8];
        g_offsets[i] = o;
        g_cursor[i]  = o;
    }
}

__global__ void scatter_kernel(const int* __restrict__ src,
                               const int* __restrict__ dst,
                               const float* __restrict__ vals, int E) {
    int e = blockIdx.x * blockDim.x + threadIdx.x;
    if (e < E) {
        int d = dst[e];
        int pos = atomicAdd(&g_cursor[d], 1);
        g_edges[pos] = make_int2(src[e], __float_as_int(vals[e]));
    }
}

// ---------------------------------------------------------------------------
// GEMM: g_h = x @ W  via bf16x3 split tensor-core MMA (no bias).
//   Block 64(M) x 128(N), BK=32. 8 warps (4 M x 2 N), 16x64 per warp.
// ---------------------------------------------------------------------------
#define BM 64
#define BN 128
#define BK 32

__global__ __launch_bounds__(256)
void gemm_tc_kernel(const float* __restrict__ X, int M) {
    __shared__ __align__(16) __nv_bfloat16 AsHi[BM][40];
    __shared__ __align__(16) __nv_bfloat16 AsLo[BM][40];
    __shared__ __align__(16) __nv_bfloat16 BsHi[BK][136];
    __shared__ __align__(16) __nv_bfloat16 BsLo[BK][136];
    __shared__ float patch[8][16][20];   // tail-block staging only

    const int t = threadIdx.x;
    const int blockRow = blockIdx.x * BM;
    const int w = t >> 5;
    const int warpM = w >> 1;
    const int warpN = w & 1;

    wmma::fragment<wmma::accumulator, 16, 16, 16, float> acc[4];
#pragma unroll
    for (int n = 0; n < 4; n++) wmma::fill_fragment(acc[n], 0.0f);

    for (int k0 = 0; k0 < IN_F; k0 += BK) {
        // A tile: 64x32 fp32 -> hi/lo bf16 (converted once globally per element)
#pragma unroll
        for (int i = 0; i < 2; i++) {
            int idx = t + i * 256;
            int arow = idx >> 3;
            int acol = (idx & 7) * 4;
            int grow = blockRow + arow;
            float4 v = make_float4(0.f, 0.f, 0.f, 0.f);
            if (grow < M)
                v = *reinterpret_cast<const float4*>(X + (size_t)grow * IN_F + k0 + acol);
            float vv[4] = {v.x, v.y, v.z, v.w};
#pragma unroll
            for (int j = 0; j < 4; j++) {
                __nv_bfloat16 hi = __float2bfloat16(vv[j]);
                __nv_bfloat16 lo = __float2bfloat16(vv[j] - __bfloat162float(hi));
                AsHi[arow][acol + j] = hi;
                AsLo[arow][acol + j] = lo;
            }
        }
        // B tile: 32x128 bf16 direct copy from precomputed hi/lo (uint4 = 8 bf16)
#pragma unroll
        for (int i = 0; i < 2; i++) {
            int idx = t + i * 256;              // 0..511
            int brow = idx >> 4;                // 0..31
            int bcol = (idx & 15) * 8;          // 0..120
            uint4 vh = *reinterpret_cast<const uint4*>(g_Whi + (size_t)(k0 + brow) * OUT_F + bcol);
            uint4 vl = *reinterpret_cast<const uint4*>(g_Wlo + (size_t)(k0 + brow) * OUT_F + bcol);
            *reinterpret_cast<uint4*>(&BsHi[brow][bcol]) = vh;
            *reinterpret_cast<uint4*>(&BsLo[brow][bcol]) = vl;
        }
        __syncthreads();

#pragma unroll
        for (int kk = 0; kk < BK; kk += 16) {
            wmma::fragment<wmma::matrix_a, 16, 16, 16, __nv_bfloat16, wmma::row_major> aHi, aLo;
            wmma::load_matrix_sync(aHi, &AsHi[warpM * 16][kk], 40);
            wmma::load_matrix_sync(aLo, &AsLo[warpM * 16][kk], 40);
#pragma unroll
            for (int n = 0; n < 4; n++) {
                wmma::fragment<wmma::matrix_b, 16, 16, 16, __nv_bfloat16, wmma::row_major> bHi, bLo;
                int col = warpN * 64 + n * 16;
                wmma::load_matrix_sync(bHi, &BsHi[kk][col], 136);
                wmma::load_matrix_sync(bLo, &BsLo[kk][col], 136);
                wmma::mma_sync(acc[n], aHi, bHi, acc[n]);
                wmma::mma_sync(acc[n], aHi, bLo, acc[n]);
                wmma::mma_sync(acc[n], aLo, bHi, acc[n]);
            }
        }
        __syncthreads();
    }

    const int rowBase = blockRow + warpM * 16;
    if (blockRow + BM <= M) {
        // fast path: direct store to global
#pragma unroll
        for (int n = 0; n < 4; n++) {
            int col = warpN * 64 + n * 16;
            wmma::store_matrix_sync(&g_h[(size_t)rowBase * OUT_F + col], acc[n],
                                    OUT_F, wmma::mem_row_major);
        }
    } else {
        // tail block: stage via smem, guard rows
        const int lane = t & 31;
#pragma unroll
        for (int n = 0; n < 4; n++) {
            wmma::store_matrix_sync(&patch[w][0][0], acc[n], 20, wmma::mem_row_major);
            __syncwarp();
            int r = lane >> 1;
            int cbase = (lane & 1) * 8;
            int grow = rowBase + r;
            int gcol = warpN * 64 + n * 16 + cbase;
            if (grow < M) {
#pragma unroll
                for (int j = 0; j < 2; j++) {
                    float4 v;
                    v.x = patch[w][r][cbase + j * 4 + 0];
                    v.y = patch[w][r][cbase + j * 4 + 1];
                    v.z = patch[w][r][cbase + j * 4 + 2];
                    v.w = patch[w][r][cbase + j * 4 + 3];
                    *reinterpret_cast<float4*>(&g_h[(size_t)grow * OUT_F + gcol + j * 4]) = v;
                }
            }
            __syncwarp();
        }
    }
}

// ---------------------------------------------------------------------------
// SpMM: warp per dst node over its sorted edge segment. No atomics.
//   out[i] = sum(val * g_h[src]) + (sum val) * bias
// ---------------------------------------------------------------------------
__global__ __launch_bounds__(256)
void spmm_kernel(const float* __restrict__ bias, float* __restrict__ out) {
    int node = (blockIdx.x * 256 + threadIdx.x) >> 5;
    int lane = threadIdx.x & 31;
    if (node >= N_NODES) return;

    int start = g_offsets[node];
    int cnt   = g_hist[node];

    float4 acc = make_float4(0.f, 0.f, 0.f, 0.f);
    float sumv = 0.f;

    for (int base = 0; base < cnt; base += 32) {
        int n = cnt - base;
        if (n > 32) n = 32;
        int2 p = make_int2(0, 0);
        if (lane < n) p = g_edges[start + base + lane];
        for (int j = 0; j < n; j++) {
            int   s  = __shfl_sync(0xffffffffu, p.x, j);
            float vi = __int_as_float(__shfl_sync(0xffffffffu, p.y, j));
            float4 m = *reinterpret_cast<const float4*>(g_h + (size_t)s * OUT_F + lane * 4);
            acc.x = fmaf(vi, m.x, acc.x);
            acc.y = fmaf(vi, m.y, acc.y);
            acc.z = fmaf(vi, m.z, acc.z);
            acc.w = fmaf(vi, m.w, acc.w);
            sumv += vi;
        }
    }

    float4 b = *reinterpret_cast<const float4*>(bias + lane * 4);
    float4 o;
    o.x = fmaf(sumv, b.x, acc.x);
    o.y = fmaf(sumv, b.y, acc.y);
    o.z = fmaf(sumv, b.z, acc.z);
    o.w = fmaf(sumv, b.w, acc.w);
    *reinterpret_cast<float4*>(out + (size_t)node * OUT_F + lane * 4) = o;
}

// ---------------------------------------------------------------------------
// Launch. Inputs: x, edge_src, edge_dst, edge_vals, weight, bias
// Order chosen so ncu (-s 5 -c 1) profiles the GEMM (launch #6).
// ---------------------------------------------------------------------------
extern "C" void kernel_launch(void* const* d_in, const int* in_sizes, int n_in,
                              void* d_out, int out_size) {
    const float* x        = (const float*)d_in[0];
    const int*   edge_src = (const int*)d_in[1];
    const int*   edge_dst = (const int*)d_in[2];
    const float* edge_val = (const float*)d_in[3];
    const float* weight   = (const float*)d_in[4];
    const float* bias     = (const float*)d_in[5];
    float*       out      = (float*)d_out;

    const int M = in_sizes[0] / IN_F;        // 100000
    const int E = in_sizes[1];               // 3200000
    const int nScanBlocks = (N_NODES + 255) / 256;   // 391

    // 1) W split (independent)
    convert_w_kernel<<<(IN_F * OUT_F + 255) / 256, 256>>>(weight);
    // 2-5) histogram + scan
    zero_hist_kernel<<<256, 256>>>();
    hist_kernel<<<(E + 255) / 256, 256>>>(edge_dst, E);
    scan1_kernel<<<nScanBlocks, 256>>>(N_NODES);
    scan2_kernel<<<1, 512>>>(nScanBlocks);
    // 6) GEMM (this is the launch ncu profiles)
    gemm_tc_kernel<<<(M + BM - 1) / BM, 256>>>(x, M);
    // 7-8) finish sort
    scan3_kernel<<<nScanBlocks, 256>>>(N_NODES);
    scatter_kernel<<<(E + 255) / 256, 256>>>(edge_src, edge_dst, edge_val, E);
    // 9) segmented SpMM + bias
    spmm_kernel<<<(N_NODES * 32 + 255) / 256, 256>>>(bias, out);
}

// round 10
// speedup vs baseline: 2.1082x; 1.0966x over previous
#include <cuda_runtime.h>
#include <cuda_bf16.h>
#include <cuda_fp16.h>
#include <mma.h>
#include <cstdint>

using namespace nvcuda;

#define N_NODES 100000
#define IN_F    256
#define OUT_F   128
#define N_EDGES 3200000

// ---- scratch (device globals per allocation rules) ----
__device__ __align__(256) __half g_hh[(size_t)N_NODES * OUT_F];  // xW in fp16, 25.6 MB
__device__ int2         g_edges[N_EDGES];                 // dst-sorted (src, valbits), 25.6 MB
__device__ int          g_hist[N_NODES];
__device__ int          g_locExc[N_NODES];
__device__ int          g_blockSums[512];
__device__ int          g_offsets[N_NODES];
__device__ int          g_cursor[N_NODES];
__device__ __nv_bfloat16 g_Whi[IN_F * OUT_F];
__device__ __nv_bfloat16 g_Wlo[IN_F * OUT_F];

// ---------------------------------------------------------------------------
// W -> (hi, lo) bf16 split, done once (32K elements)
// ---------------------------------------------------------------------------
__global__ void convert_w_kernel(const float* __restrict__ W) {
    int i = blockIdx.x * blockDim.x + threadIdx.x;
    if (i < IN_F * OUT_F) {
        float w = W[i];
        __nv_bfloat16 hi = __float2bfloat16(w);
        __nv_bfloat16 lo = __float2bfloat16(w - __bfloat162float(hi));
        g_Whi[i] = hi;
        g_Wlo[i] = lo;
    }
}

// ---------------------------------------------------------------------------
// Counting sort of edges by dst
// ---------------------------------------------------------------------------
__global__ void zero_hist_kernel() {
    int i = blockIdx.x * blockDim.x + threadIdx.x;
    int stride = gridDim.x * blockDim.x;
    for (; i < N_NODES; i += stride) g_hist[i] = 0;
}

__global__ void hist_kernel(const int* __restrict__ dst, int E) {
    int e = blockIdx.x * blockDim.x + threadIdx.x;
    if (e < E) atomicAdd(&g_hist[dst[e]], 1);
}

__global__ void scan1_kernel(int n) {
    __shared__ int sm[256];
    int i = blockIdx.x * 256 + threadIdx.x;
    int v = (i < n) ? g_hist[i] : 0;
    sm[threadIdx.x] = v;
    __syncthreads();
#pragma unroll
    for (int off = 1; off < 256; off <<= 1) {
        int add = (threadIdx.x >= off) ? sm[threadIdx.x - off] : 0;
        __syncthreads();
        sm[threadIdx.x] += add;
        __syncthreads();
    }
    if (i < n) g_locExc[i] = sm[threadIdx.x] - v;     // exclusive
    if (threadIdx.x == 255) g_blockSums[blockIdx.x] = sm[255];
}

__global__ void scan2_kernel(int nb) {
    __shared__ int sm[512];
    int t = threadIdx.x;
    int v = (t < nb) ? g_blockSums[t] : 0;
    sm[t] = v;
    __syncthreads();
#pragma unroll
    for (int off = 1; off < 512; off <<= 1) {
        int add = (t >= off) ? sm[t - off] : 0;
        __syncthreads();
        sm[t] += add;
        __syncthreads();
    }
    g_blockSums[t] = sm[t] - v;                        // exclusive
}

__global__ void scan3_kernel(int n) {
    int i = blockIdx.x * blockDim.x + threadIdx.x;
    if (i < n) {
        int o = g_locExc[i] + g_blockSums[i >> 8];
        g_offsets[i] = o;
        g_cursor[i]  = o;
    }
}

__global__ void scatter_kernel(const int* __restrict__ src,
                               const int* __restrict__ dst,
                               const float* __restrict__ vals, int E) {
    int e = blockIdx.x * blockDim.x + threadIdx.x;
    if (e < E) {
        int d = dst[e];
        int pos = atomicAdd(&g_cursor[d], 1);
        g_edges[pos] = make_int2(src[e], __float_as_int(vals[e]));
    }
}

// ---------------------------------------------------------------------------
// GEMM: g_hh = fp16(x @ W)  via bf16x3 split tensor-core MMA (no bias).
//   Block 64(M) x 128(N), BK=32. 8 warps (4 M x 2 N), 16x64 per warp.
// ---------------------------------------------------------------------------
#define BM 64
#define BN 128
#define BK 32

__global__ __launch_bounds__(256)
void gemm_tc_kernel(const float* __restrict__ X, int M) {
    __shared__ __align__(16) __nv_bfloat16 AsHi[BM][40];
    __shared__ __align__(16) __nv_bfloat16 AsLo[BM][40];
    __shared__ __align__(16) __nv_bfloat16 BsHi[BK][136];
    __shared__ __align__(16) __nv_bfloat16 BsLo[BK][136];
    __shared__ float patch[8][16][20];   // per-warp staging for fp16 convert

    const int t = threadIdx.x;
    const int blockRow = blockIdx.x * BM;
    const int w = t >> 5;
    const int warpM = w >> 1;
    const int warpN = w & 1;

    wmma::fragment<wmma::accumulator, 16, 16, 16, float> acc[4];
#pragma unroll
    for (int n = 0; n < 4; n++) wmma::fill_fragment(acc[n], 0.0f);

    for (int k0 = 0; k0 < IN_F; k0 += BK) {
        // A tile: 64x32 fp32 -> hi/lo bf16
#pragma unroll
        for (int i = 0; i < 2; i++) {
            int idx = t + i * 256;
            int arow = idx >> 3;
            int acol = (idx & 7) * 4;
            int grow = blockRow + arow;
            float4 v = make_float4(0.f, 0.f, 0.f, 0.f);
            if (grow < M)
                v = *reinterpret_cast<const float4*>(X + (size_t)grow * IN_F + k0 + acol);
            float vv[4] = {v.x, v.y, v.z, v.w};
#pragma unroll
            for (int j = 0; j < 4; j++) {
                __nv_bfloat16 hi = __float2bfloat16(vv[j]);
                __nv_bfloat16 lo = __float2bfloat16(vv[j] - __bfloat162float(hi));
                AsHi[arow][acol + j] = hi;
                AsLo[arow][acol + j] = lo;
            }
        }
        // B tile: 32x128 bf16 copy from precomputed hi/lo
#pragma unroll
        for (int i = 0; i < 2; i++) {
            int idx = t + i * 256;
            int brow = idx >> 4;
            int bcol = (idx & 15) * 8;
            uint4 vh = *reinterpret_cast<const uint4*>(g_Whi + (size_t)(k0 + brow) * OUT_F + bcol);
            uint4 vl = *reinterpret_cast<const uint4*>(g_Wlo + (size_t)(k0 + brow) * OUT_F + bcol);
            *reinterpret_cast<uint4*>(&BsHi[brow][bcol]) = vh;
            *reinterpret_cast<uint4*>(&BsLo[brow][bcol]) = vl;
        }
        __syncthreads();

#pragma unroll
        for (int kk = 0; kk < BK; kk += 16) {
            wmma::fragment<wmma::matrix_a, 16, 16, 16, __nv_bfloat16, wmma::row_major> aHi, aLo;
            wmma::load_matrix_sync(aHi, &AsHi[warpM * 16][kk], 40);
            wmma::load_matrix_sync(aLo, &AsLo[warpM * 16][kk], 40);
#pragma unroll
            for (int n = 0; n < 4; n++) {
                wmma::fragment<wmma::matrix_b, 16, 16, 16, __nv_bfloat16, wmma::row_major> bHi, bLo;
                int col = warpN * 64 + n * 16;
                wmma::load_matrix_sync(bHi, &BsHi[kk][col], 136);
                wmma::load_matrix_sync(bLo, &BsLo[kk][col], 136);
                wmma::mma_sync(acc[n], aHi, bHi, acc[n]);
                wmma::mma_sync(acc[n], aHi, bLo, acc[n]);
                wmma::mma_sync(acc[n], aLo, bHi, acc[n]);
            }
        }
        __syncthreads();
    }

    // Epilogue: stage via smem, convert to fp16, store 8 halves (16B) per lane.
    const int lane = t & 31;
    const int rowBase = blockRow + warpM * 16;
#pragma unroll
    for (int n = 0; n < 4; n++) {
        wmma::store_matrix_sync(&patch[w][0][0], acc[n], 20, wmma::mem_row_major);
        __syncwarp();
        int r = lane >> 1;                 // 0..15
        int cbase = (lane & 1) * 8;        // 0 or 8
        int grow = rowBase + r;
        int gcol = warpN * 64 + n * 16 + cbase;
        if (grow < M) {
            __half2 h01 = __floats2half2_rn(patch[w][r][cbase + 0], patch[w][r][cbase + 1]);
            __half2 h23 = __floats2half2_rn(patch[w][r][cbase + 2], patch[w][r][cbase + 3]);
            __half2 h45 = __floats2half2_rn(patch[w][r][cbase + 4], patch[w][r][cbase + 5]);
            __half2 h67 = __floats2half2_rn(patch[w][r][cbase + 6], patch[w][r][cbase + 7]);
            uint4 pk;
            pk.x = *reinterpret_cast<uint32_t*>(&h01);
            pk.y = *reinterpret_cast<uint32_t*>(&h23);
            pk.z = *reinterpret_cast<uint32_t*>(&h45);
            pk.w = *reinterpret_cast<uint32_t*>(&h67);
            *reinterpret_cast<uint4*>(&g_hh[(size_t)grow * OUT_F + gcol]) = pk;
        }
        __syncwarp();
    }
}

// ---------------------------------------------------------------------------
// SpMM: warp per dst node over its sorted edge segment. No atomics.
//   out[i] = sum(val * h[src]) + (sum val) * bias   (h gathered as fp16)
// ---------------------------------------------------------------------------
__global__ __launch_bounds__(256)
void spmm_kernel(const float* __restrict__ bias, float* __restrict__ out) {
    int node = (blockIdx.x * 256 + threadIdx.x) >> 5;
    int lane = threadIdx.x & 31;
    if (node >= N_NODES) return;

    int start = g_offsets[node];
    int cnt   = g_hist[node];

    float4 acc = make_float4(0.f, 0.f, 0.f, 0.f);
    float sumv = 0.f;

    for (int base = 0; base < cnt; base += 32) {
        int n = cnt - base;
        if (n > 32) n = 32;
        int2 p = make_int2(0, 0);
        if (lane < n) p = g_edges[start + base + lane];
        for (int j = 0; j < n; j++) {
            int   s  = __shfl_sync(0xffffffffu, p.x, j);
            float vi = __int_as_float(__shfl_sync(0xffffffffu, p.y, j));
            // 4 halves (8B) per lane -> 256B per row per warp
            uint2 raw = *reinterpret_cast<const uint2*>(g_hh + (size_t)s * OUT_F + lane * 4);
            __half2 h01 = *reinterpret_cast<__half2*>(&raw.x);
            __half2 h23 = *reinterpret_cast<__half2*>(&raw.y);
            float2 f01 = __half22float2(h01);
            float2 f23 = __half22float2(h23);
            acc.x = fmaf(vi, f01.x, acc.x);
            acc.y = fmaf(vi, f01.y, acc.y);
            acc.z = fmaf(vi, f23.x, acc.z);
            acc.w = fmaf(vi, f23.y, acc.w);
            sumv += vi;
        }
    }

    float4 b = *reinterpret_cast<const float4*>(bias + lane * 4);
    float4 o;
    o.x = fmaf(sumv, b.x, acc.x);
    o.y = fmaf(sumv, b.y, acc.y);
    o.z = fmaf(sumv, b.z, acc.z);
    o.w = fmaf(sumv, b.w, acc.w);
    *reinterpret_cast<float4*>(out + (size_t)node * OUT_F + lane * 4) = o;
}

// ---------------------------------------------------------------------------
// Launch. Inputs: x, edge_src, edge_dst, edge_vals, weight, bias
// ---------------------------------------------------------------------------
extern "C" void kernel_launch(void* const* d_in, const int* in_sizes, int n_in,
                              void* d_out, int out_size) {
    const float* x        = (const float*)d_in[0];
    const int*   edge_src = (const int*)d_in[1];
    const int*   edge_dst = (const int*)d_in[2];
    const float* edge_val = (const float*)d_in[3];
    const float* weight   = (const float*)d_in[4];
    const float* bias     = (const float*)d_in[5];
    float*       out      = (float*)d_out;

    const int M = in_sizes[0] / IN_F;        // 100000
    const int E = in_sizes[1];               // 3200000
    const int nScanBlocks = (N_NODES + 255) / 256;   // 391

    convert_w_kernel<<<(IN_F * OUT_F + 255) / 256, 256>>>(weight);
    zero_hist_kernel<<<256, 256>>>();
    hist_kernel<<<(E + 255) / 256, 256>>>(edge_dst, E);
    scan1_kernel<<<nScanBlocks, 256>>>(N_NODES);
    scan2_kernel<<<1, 512>>>(nScanBlocks);
    gemm_tc_kernel<<<(M + BM - 1) / BM, 256>>>(x, M);
    scan3_kernel<<<nScanBlocks, 256>>>(N_NODES);
    scatter_kernel<<<(E + 255) / 256, 256>>>(edge_src, edge_dst, edge_val, E);
    spmm_kernel<<<(N_NODES * 32 + 255) / 256, 256>>>(bias, out);
}